// round 14
// baseline (speedup 1.0000x reference)
#include <cuda_runtime.h>
#include <cuda_bf16.h>
#include <cstdint>
#include <cstddef>

#define S_LEN 2048
#define B_SZ  128
#define H_SZ  128
#define I_SZ  64
#define O_SZ  64
#define GC    512

// Scratch (device globals per allocation rules)
__device__ float g_pre[(size_t)S_LEN * B_SZ * GC];   // [t][b][gcol]  512 MB
__device__ float g_hs [(size_t)B_SZ * S_LEN * H_SZ]; // [b][t][h]     128 MB

typedef unsigned long long ull;

__device__ __forceinline__ ull pk2(float lo, float hi) {
    ull r;
    asm("mov.b64 %0, {%1, %2};" : "=l"(r)
        : "r"(__float_as_uint(lo)), "r"(__float_as_uint(hi)));
    return r;
}
__device__ __forceinline__ void upk2(ull v, float& lo, float& hi) {
    unsigned int a, b;
    asm("mov.b64 {%0, %1}, %2;" : "=r"(a), "=r"(b) : "l"(v));
    lo = __uint_as_float(a); hi = __uint_as_float(b);
}
#define FMA2(acc, va, vb) asm("fma.rn.f32x2 %0, %1, %2, %0;" : "+l"(acc) : "l"(va), "l"(vb))
#define ADD2(acc, vb)     asm("add.rn.f32x2 %0, %1, %0;"     : "+l"(acc) : "l"(vb))

__device__ __forceinline__ float sigm(float v)  { return __fdividef(1.0f, 1.0f + __expf(-v)); }
__device__ __forceinline__ float tanhx(float v) { return 1.0f - __fdividef(2.0f, __expf(2.0f * v) + 1.0f); }

__device__ __forceinline__ void csync() {
    asm volatile("barrier.cluster.arrive.aligned;" ::: "memory");
    asm volatile("barrier.cluster.wait.aligned;"   ::: "memory");
}
__device__ __forceinline__ void stc32(uint32_t local_addr, uint32_t rk, float v) {
    uint32_t ra;
    asm("mapa.shared::cluster.u32 %0, %1, %2;" : "=r"(ra) : "r"(local_addr), "r"(rk));
    asm volatile("st.shared::cluster.f32 [%0], %1;" :: "r"(ra), "f"(v) : "memory");
}
__device__ __forceinline__ void stc64(uint32_t local_addr, uint32_t rk, ull v) {
    uint32_t ra;
    asm("mapa.shared::cluster.u32 %0, %1, %2;" : "=r"(ra) : "r"(local_addr), "r"(rk));
    asm volatile("st.shared::cluster.b64 [%0], %1;" :: "r"(ra), "l"(v) : "memory");
}

// ---------------------------------------------------------------------------
// Phase 1: g_pre[t][b][gcol] = sum_i x[b][i][t] * Wx_out[i][gcol]
// ---------------------------------------------------------------------------
__global__ void __launch_bounds__(256) pre_kernel(const float* __restrict__ x,
                                                  const float* __restrict__ Wx)
{
    __shared__ __align__(16) float sX[64][65];  // [t][i]
    __shared__ __align__(16) float sW[64][68];  // [i][c]
    const int t0  = blockIdx.x * 64;
    const int c0  = blockIdx.y * 64;
    const int b   = blockIdx.z;
    const int tid = threadIdx.x;

    for (int idx = tid; idx < 4096; idx += 256) {
        int hi = idx >> 6, lo = idx & 63;
        sX[lo][hi] = x[(size_t)b * (I_SZ * S_LEN) + (size_t)hi * S_LEN + t0 + lo];
        sW[hi][lo] = Wx[hi * GC + c0 + lo];
    }
    __syncthreads();

    const int ty = tid >> 4, tx = tid & 15;
    const int r0 = ty * 4, c4 = tx * 4;
    float acc[4][4] = {};
#pragma unroll 8
    for (int k = 0; k < 64; ++k) {
        float4 bv = *(const float4*)&sW[k][c4];
#pragma unroll
        for (int u = 0; u < 4; ++u) {
            float a = sX[r0 + u][k];
            acc[u][0] += a * bv.x; acc[u][1] += a * bv.y;
            acc[u][2] += a * bv.z; acc[u][3] += a * bv.w;
        }
    }
#pragma unroll
    for (int u = 0; u < 4; ++u) {
        float4 v = make_float4(acc[u][0], acc[u][1], acc[u][2], acc[u][3]);
        *(float4*)&g_pre[((size_t)(t0 + r0 + u) * B_SZ + b) * GC + c0 + c4] = v;
    }
}

// ---------------------------------------------------------------------------
// Phase 2: recurrence. 32 clusters x 4 CTAs, 256 threads/CTA (split-K).
// CTA rank r owns gate columns gcol = g*128 + r*32 + (c&31), c = tid&127.
// half = tid>>7 covers k in [half*64, half*64+64); partials reduced via smem.
// Weights smem layout: sWh [c][k] pad 132 (LDS.128, 4 k per load);
// sWxh [c][(wx,wh) interleaved over k] pad 260 — one FMA2 does x*wx + h*wh.
// ---------------------------------------------------------------------------
#define OFF_WXH 16896                 // sWh = 128*132
#define OFF_H   (OFF_WXH + 33280)     // sWxh = 128*260
#define OFF_XH  (OFF_H   + 512)      // sH  = [k][4]
#define OFF_G   (OFF_XH  + 1024)     // sXH = [k][b][2]
#define OFF_P   (OFF_G   + 640)      // sG  = [c][5]
#define REC_SMEM_FLOATS (OFF_P + 1280)   // sP = [c][10] (ull stride 5)
#define REC_SMEM_BYTES  (REC_SMEM_FLOATS * 4)

__global__ void __cluster_dims__(4, 1, 1) __launch_bounds__(256, 1)
rec_kernel(const float* __restrict__ Wh_out, const float* __restrict__ Wx_in,
           const float* __restrict__ Wh_in,  const float* __restrict__ b_out,
           const float* __restrict__ b_in)
{
    extern __shared__ __align__(16) float sm[];
    float* sWh  = sm;
    float* sWxh = sm + OFF_WXH;
    float* sH   = sm + OFF_H;
    float* sXH  = sm + OFF_XH;
    float* sG   = sm + OFF_G;
    ull*   sPu  = (ull*)(sm + OFF_P);

    const int tid = threadIdx.x;
    unsigned int rank;
    asm("mov.u32 %0, %%cluster_ctarank;" : "=r"(rank));
    const int bb   = blockIdx.x & ~3;     // batch base of this cluster
    const int c    = tid & 127;           // gate-column slot within CTA
    const int half = tid >> 7;            // k-half
    const int k0   = half * 64;

    // ---- load weights (coalesced global reads, scattered smem stores) ----
    for (int idx = tid; idx < 128 * 128; idx += 256) {
        int k  = idx >> 7;
        int cc = idx & 127;
        int gcol = ((cc >> 5) << 7) + (int)rank * 32 + (cc & 31);
        sWh [cc * 132 + k]         = Wh_out[k * GC + gcol];
        sWxh[cc * 260 + 2 * k]     = Wx_in [k * GC + gcol];
        sWxh[cc * 260 + 2 * k + 1] = Wh_in [k * GC + gcol];
    }
    if (tid < 128) {
        sH[tid] = 0.0f; sH[tid + 128] = 0.0f; sH[tid + 256] = 0.0f; sH[tid + 384] = 0.0f;
    }
    const int gcolc = ((c >> 5) << 7) + (int)rank * 32 + (c & 31);
    const float bo = b_out[gcolc];
    const float bi = b_in[gcolc];

    // Epilogue role (tid<128): thread (b2, jj) owns state for batch bb+b2, H-col J
    const int b2 = tid >> 5, jj = tid & 31;
    const int J  = (int)rank * 32 + jj;
    const uint32_t aXH = (uint32_t)__cvta_generic_to_shared(&sXH[J * 8 + b2 * 2]);
    const uint32_t aH  = (uint32_t)__cvta_generic_to_shared(&sH [J * 4 + b2]);

    float c_st = 0.0f, cn_st = 0.0f, o_g = 0.0f;

    csync();  // weights + h0 ready cluster-wide

    const float* preb = g_pre + (size_t)bb * GC + gcolc;

    for (int t = 0; t < S_LEN; ++t) {
        float p0 = 0.f, p1 = 0.f, p2 = 0.f, p3 = 0.f;
        if (tid < 128) {        // prefetch pre-activations (consumed after GEMM)
            const float* pp = preb + (size_t)t * (B_SZ * GC);
            p0 = pp[0]; p1 = pp[GC]; p2 = pp[2 * GC]; p3 = pp[3 * GC];
        }

        // ---- outer GEMM partial: acc[b] += h[b][k] * Wh[k][c], k in half ----
        ull a01 = 0, a23 = 0;
        {
            const float* wp = sWh + c * 132 + k0;
            const float* hp = sH + k0 * 4;
#pragma unroll
            for (int i = 0; i < 16; ++i) {
                float4 wv = *(const float4*)(wp + 4 * i);
                ulonglong2 h0v = *(const ulonglong2*)(hp + 16 * i);
                ulonglong2 h1v = *(const ulonglong2*)(hp + 16 * i + 4);
                ulonglong2 h2v = *(const ulonglong2*)(hp + 16 * i + 8);
                ulonglong2 h3v = *(const ulonglong2*)(hp + 16 * i + 12);
                ull w0 = pk2(wv.x, wv.x), w1 = pk2(wv.y, wv.y);
                ull w2 = pk2(wv.z, wv.z), w3 = pk2(wv.w, wv.w);
                FMA2(a01, h0v.x, w0); FMA2(a23, h0v.y, w0);
                FMA2(a01, h1v.x, w1); FMA2(a23, h1v.y, w1);
                FMA2(a01, h2v.x, w2); FMA2(a23, h2v.y, w2);
                FMA2(a01, h3v.x, w3); FMA2(a23, h3v.y, w3);
            }
        }
        if (half) { sPu[c * 5] = a01; sPu[c * 5 + 1] = a23; }
        __syncthreads();
        if (!half) {
            ADD2(a01, sPu[c * 5]); ADD2(a23, sPu[c * 5 + 1]);
            float a0, a1, a2, a3;
            upk2(a01, a0, a1); upk2(a23, a2, a3);
            sG[c * 5 + 0] = a0 + p0 + bo;
            sG[c * 5 + 1] = a1 + p1 + bo;
            sG[c * 5 + 2] = a2 + p2 + bo;
            sG[c * 5 + 3] = a3 + p3 + bo;
        }
        __syncthreads();

        // ---- epilogue 1: gates -> (x_in, h_in) packed, broadcast cluster-wide ----
        if (tid < 128) {
            float gi = sG[(jj     ) * 5 + b2];
            float gf = sG[(32 + jj) * 5 + b2];
            float go = sG[(64 + jj) * 5 + b2];
            float gg = sG[(96 + jj) * 5 + b2];
            o_g = sigm(go);
            float x_in = sigm(gi) * tanhx(gg);
            float h_in = sigm(gf) * c_st;
            ull xh = pk2(x_in, h_in);
#pragma unroll
            for (int rk = 0; rk < 4; ++rk) stc64(aXH, rk, xh);
        }
        csync();

        // ---- inner GEMM partial: one FMA2 = x*wx + h*wh across halves ----
        ull ab0 = 0, ab1 = 0, ab2 = 0, ab3 = 0;
        {
            const float* wp = sWxh + c * 260 + 2 * k0;
            const float* xp = sXH + k0 * 8;
#pragma unroll
            for (int i = 0; i < 32; ++i) {        // 2 k per iteration
                float4 wv = *(const float4*)(wp + 4 * i);
                ull w0 = pk2(wv.x, wv.y), w1 = pk2(wv.z, wv.w);
                ulonglong2 qa = *(const ulonglong2*)(xp + 16 * i);
                ulonglong2 qb = *(const ulonglong2*)(xp + 16 * i + 4);
                FMA2(ab0, qa.x, w0); FMA2(ab1, qa.y, w0);
                FMA2(ab2, qb.x, w0); FMA2(ab3, qb.y, w0);
                ulonglong2 qc = *(const ulonglong2*)(xp + 16 * i + 8);
                ulonglong2 qd = *(const ulonglong2*)(xp + 16 * i + 12);
                FMA2(ab0, qc.x, w1); FMA2(ab1, qc.y, w1);
                FMA2(ab2, qd.x, w1); FMA2(ab3, qd.y, w1);
            }
        }
        if (half) {
            sPu[c * 5]     = ab0; sPu[c * 5 + 1] = ab1;
            sPu[c * 5 + 2] = ab2; sPu[c * 5 + 3] = ab3;
        }
        __syncthreads();
        if (!half) {
            ADD2(ab0, sPu[c * 5]);     ADD2(ab1, sPu[c * 5 + 1]);
            ADD2(ab2, sPu[c * 5 + 2]); ADD2(ab3, sPu[c * 5 + 3]);
            float u, v;
            upk2(ab0, u, v); sG[c * 5 + 0] = u + v + bi;
            upk2(ab1, u, v); sG[c * 5 + 1] = u + v + bi;
            upk2(ab2, u, v); sG[c * 5 + 2] = u + v + bi;
            upk2(ab3, u, v); sG[c * 5 + 3] = u + v + bi;
        }
        __syncthreads();

        // ---- epilogue 2: inner LSTM update, h_new broadcast + store ----
        if (tid < 128) {
            float ii = sG[(jj     ) * 5 + b2];
            float fi = sG[(32 + jj) * 5 + b2];
            float oi = sG[(64 + jj) * 5 + b2];
            float g2 = sG[(96 + jj) * 5 + b2];
            cn_st = sigm(fi) * cn_st + sigm(ii) * tanhx(g2);
            c_st  = sigm(oi) * tanhx(cn_st);
            float h_new = o_g * tanhx(c_st);
            g_hs[((size_t)(bb + b2) * S_LEN + t) * H_SZ + J] = h_new;
#pragma unroll
            for (int rk = 0; rk < 4; ++rk) stc32(aH, rk, h_new);
        }
        csync();
    }
}

// ---------------------------------------------------------------------------
// Phase 3: out[m][n] = g_hs[m][:] @ W_lin[n][:] + b_lin[n],  m = b*S + s
// ---------------------------------------------------------------------------
__global__ void __launch_bounds__(256) lin_kernel(const float* __restrict__ W_lin,
                                                  const float* __restrict__ b_lin,
                                                  float* __restrict__ out)
{
    __shared__ __align__(16) float sA[64][68];  // [row][k]
    __shared__ __align__(16) float sB[64][68];  // [k][n]
    const int m0  = blockIdx.x * 64;
    const int tid = threadIdx.x;
    const int ty = tid >> 4, tx = tid & 15;
    const int r0 = ty * 4, c4 = tx * 4;

    float acc[4][4] = {};
    for (int kb = 0; kb < H_SZ; kb += 64) {
        for (int idx = tid; idx < 4096; idx += 256) {
            int hi = idx >> 6, lo = idx & 63;
            sA[hi][lo] = g_hs[(size_t)(m0 + hi) * H_SZ + kb + lo];
            sB[lo][hi] = W_lin[hi * H_SZ + kb + lo];
        }
        __syncthreads();
#pragma unroll 8
        for (int k = 0; k < 64; ++k) {
            float4 bv = *(const float4*)&sB[k][c4];
#pragma unroll
            for (int u = 0; u < 4; ++u) {
                float a = sA[r0 + u][k];
                acc[u][0] += a * bv.x; acc[u][1] += a * bv.y;
                acc[u][2] += a * bv.z; acc[u][3] += a * bv.w;
            }
        }
        __syncthreads();
    }
    float4 bl = *(const float4*)&b_lin[c4];
#pragma unroll
    for (int u = 0; u < 4; ++u) {
        float4 v = make_float4(acc[u][0] + bl.x, acc[u][1] + bl.y,
                               acc[u][2] + bl.z, acc[u][3] + bl.w);
        *(float4*)&out[(size_t)(m0 + r0 + u) * O_SZ + c4] = v;
    }
}

// ---------------------------------------------------------------------------
extern "C" void kernel_launch(void* const* d_in, const int* in_sizes, int n_in,
                              void* d_out, int out_size)
{
    (void)in_sizes; (void)n_in; (void)out_size;
    const float* x      = (const float*)d_in[0];
    const float* Wx_out = (const float*)d_in[1];
    const float* Wh_out = (const float*)d_in[2];
    const float* b_out  = (const float*)d_in[3];
    const float* Wx_in  = (const float*)d_in[4];
    const float* Wh_in  = (const float*)d_in[5];
    const float* b_in   = (const float*)d_in[6];
    const float* W_lin  = (const float*)d_in[7];
    const float* b_lin  = (const float*)d_in[8];
    float* out = (float*)d_out;

    pre_kernel<<<dim3(S_LEN / 64, GC / 64, B_SZ), 256>>>(x, Wx_out);

    cudaFuncSetAttribute(rec_kernel, cudaFuncAttributeMaxDynamicSharedMemorySize,
                         REC_SMEM_BYTES);
    rec_kernel<<<128, 256, REC_SMEM_BYTES>>>(Wh_out, Wx_in, Wh_in, b_out, b_in);

    lin_kernel<<<(B_SZ * S_LEN) / 64, 256>>>(W_lin, b_lin, out);
}